// round 17
// baseline (speedup 1.0000x reference)
#include <cuda_runtime.h>
#include <math.h>
#include <stdint.h>

#define NN 50000
#define NE 800000
#define HD  256
#define EPS_BN 1e-5f
#define SLOPE_LR 0.01f
#define NBY 391                       // ceil(NN/128) row-blocks per GEMM
#define APAD 44                       // floats per smem row: 176B = 16B-aligned, conflict-free
#define GEMM_BUF (2 * 128 * APAD)     // floats per double-buffer slot (A tile + B tile)
#define GEMM_SMEM (2 * GEMM_BUF * 4)  // bytes: 90112

// ---------------- scratch (__device__ globals; no allocation allowed) ----------------
__device__ float g_aggr0[(size_t)NN * HD];
__device__ float g_aggr1[(size_t)NN * HD];
__device__ float g_aggr2[(size_t)NN * HD];
__device__ float g_hA[(size_t)NN * HD];
__device__ float g_hB[(size_t)NN * HD];
__device__ float g_preA[(size_t)NN * HD];
__device__ float g_preB[(size_t)NN * HD];
__device__ float g_xAt[(size_t)NN * 256];
__device__ float g_xBt[(size_t)NN * 128];
__device__ int   g_icnt[3 * NN];             // degree counts, then reused as fill cursors
__device__ int   g_roff[3 * (NN + 1)];
__device__ int   g_csr[3 * NE];
__device__ float g_WA1[HD * 640];
__device__ float g_WB1[HD * 384];
__device__ float g_WA2[HD * 768];
__device__ float g_WB2[HD * 512];
__device__ float g_bA1[HD], g_bB1[HD], g_bA2[HD], g_bB2[HD];
__device__ float g_partA[NBY * 512];         // per-row-block col sum/sumsq (A side)
__device__ float g_partB[NBY * 512];         // (B side)
__device__ float g_scA[HD], g_shA[HD], g_scB[HD], g_shB[HD];

// ---------------- utility ----------------
__device__ __forceinline__ float to_tf32(float x) {
    uint32_t u;
    asm("cvt.rna.tf32.f32 %0, %1;" : "=r"(u) : "f"(x));
    return __uint_as_float(u);
}

__device__ __forceinline__ void cp16(uint32_t dst, const void* src, int srcsize) {
    asm volatile("cp.async.ca.shared.global [%0], [%1], 16, %2;"
                 :: "r"(dst), "l"(src), "r"(srcsize));
}

__global__ void zero_int_kernel(int* __restrict__ p, int n) {
    int i = blockIdx.x * blockDim.x + threadIdx.x;
    if (i < n) p[i] = 0;
}

__global__ void count_int_kernel(const int* __restrict__ dst, int* __restrict__ cnt, int E) {
    int e = blockIdx.x * blockDim.x + threadIdx.x;
    if (e < E) atomicAdd(cnt + dst[e], 1);
}

// chunked exclusive scan: 1024 threads, 2 barriers; resets cnt for fill reuse
__global__ void scan_kernel(int* __restrict__ cnt, int* __restrict__ roff) {
    const int C = (NN + 1023) / 1024;
    int tid = threadIdx.x;
    int lane = tid & 31, wid = tid >> 5;
    int start = tid * C;
    int end = min(start + C, NN);
    int sum = 0;
    for (int i = start; i < end; i++) sum += cnt[i];

    int v = sum;
#pragma unroll
    for (int off = 1; off < 32; off <<= 1) {
        int t = __shfl_up_sync(0xffffffffu, v, off);
        if (lane >= off) v += t;
    }
    __shared__ int wsum[32];
    if (lane == 31) wsum[wid] = v;
    __syncthreads();
    if (wid == 0) {
        int w = wsum[lane];
#pragma unroll
        for (int off = 1; off < 32; off <<= 1) {
            int t = __shfl_up_sync(0xffffffffu, w, off);
            if (lane >= off) w += t;
        }
        wsum[lane] = w;
    }
    __syncthreads();
    int excl = v - sum + (wid > 0 ? wsum[wid - 1] : 0);

    int run = excl;
    for (int i = start; i < end; i++) {
        run += cnt[i];
        roff[i + 1] = run;
        cnt[i] = 0;
    }
    if (tid == 0) roff[0] = 0;
}

__global__ void fill_kernel(const int* __restrict__ src, const int* __restrict__ dst,
                            const int* __restrict__ roff, int* __restrict__ fill,
                            int* __restrict__ csr, int E) {
    int e = blockIdx.x * blockDim.x + threadIdx.x;
    if (e >= E) return;
    int d = dst[e];
    int pos = roff[d] + atomicAdd(fill + d, 1);
    csr[pos] = src[e];
}

// gather-mean over CSR, 256-dim rows (layer 1, raw features), tf32-rounded output
__global__ void gather256_kernel(const float* __restrict__ feat,
                                 const int* __restrict__ roff,
                                 const int* __restrict__ csr,
                                 float* __restrict__ out) {
    int node = blockIdx.x * 4 + (threadIdx.x >> 6);
    int lane = threadIdx.x & 63;
    if (node >= NN) return;
    int j0 = roff[node], j1 = roff[node + 1];
    const float4* f = reinterpret_cast<const float4*>(feat);
    float4 acc = make_float4(0.f, 0.f, 0.f, 0.f);
    int j = j0;
    for (; j + 1 < j1; j += 2) {
        int s0 = csr[j], s1 = csr[j + 1];
        float4 a = f[(size_t)s0 * 64 + lane];
        float4 b = f[(size_t)s1 * 64 + lane];
        acc.x += a.x; acc.y += a.y; acc.z += a.z; acc.w += a.w;
        acc.x += b.x; acc.y += b.y; acc.z += b.z; acc.w += b.w;
    }
    if (j < j1) {
        int s = csr[j];
        float4 a = f[(size_t)s * 64 + lane];
        acc.x += a.x; acc.y += a.y; acc.z += a.z; acc.w += a.w;
    }
    float r = 1.0f / (float)max(j1 - j0, 1);
    float4 o;
    o.x = to_tf32(acc.x * r); o.y = to_tf32(acc.y * r);
    o.z = to_tf32(acc.z * r); o.w = to_tf32(acc.w * r);
    reinterpret_cast<float4*>(out)[(size_t)node * 64 + lane] = o;
}

// gather-mean, 128-dim rows (layer 1, x_B)
__global__ void gather128_kernel(const float* __restrict__ feat,
                                 const int* __restrict__ roff,
                                 const int* __restrict__ csr,
                                 float* __restrict__ out) {
    int node = blockIdx.x * 8 + (threadIdx.x >> 5);
    int lane = threadIdx.x & 31;
    if (node >= NN) return;
    int j0 = roff[node], j1 = roff[node + 1];
    const float4* f = reinterpret_cast<const float4*>(feat);
    float4 acc = make_float4(0.f, 0.f, 0.f, 0.f);
    int j = j0;
    for (; j + 1 < j1; j += 2) {
        int s0 = csr[j], s1 = csr[j + 1];
        float4 a = f[(size_t)s0 * 32 + lane];
        float4 b = f[(size_t)s1 * 32 + lane];
        acc.x += a.x; acc.y += a.y; acc.z += a.z; acc.w += a.w;
        acc.x += b.x; acc.y += b.y; acc.z += b.z; acc.w += b.w;
    }
    if (j < j1) {
        int s = csr[j];
        float4 a = f[(size_t)s * 32 + lane];
        acc.x += a.x; acc.y += a.y; acc.z += a.z; acc.w += a.w;
    }
    float r = 1.0f / (float)max(j1 - j0, 1);
    float4 o;
    o.x = to_tf32(acc.x * r); o.y = to_tf32(acc.y * r);
    o.z = to_tf32(acc.z * r); o.w = to_tf32(acc.w * r);
    reinterpret_cast<float4*>(out)[(size_t)node * 32 + lane] = o;
}

// layer-2 gather: reads PRE-activation, applies BN scale/shift + LeakyReLU inline,
// then mean + tf32 round. Removes bn_apply from the gather dependency chain.
__global__ void gather256_bn_kernel(const float* __restrict__ pre,
                                    const int* __restrict__ roff,
                                    const int* __restrict__ csr,
                                    const float* __restrict__ sc,
                                    const float* __restrict__ sh,
                                    float* __restrict__ out) {
    int node = blockIdx.x * 4 + (threadIdx.x >> 6);
    int lane = threadIdx.x & 63;
    if (node >= NN) return;
    float4 a4 = reinterpret_cast<const float4*>(sc)[lane];
    float4 h4 = reinterpret_cast<const float4*>(sh)[lane];
    int j0 = roff[node], j1 = roff[node + 1];
    const float4* f = reinterpret_cast<const float4*>(pre);
    float4 acc = make_float4(0.f, 0.f, 0.f, 0.f);
    for (int j = j0; j < j1; j++) {
        int s = csr[j];
        float4 x = f[(size_t)s * 64 + lane];
        float y;
        y = a4.x * x.x + h4.x; acc.x += y > 0.f ? y : SLOPE_LR * y;
        y = a4.y * x.y + h4.y; acc.y += y > 0.f ? y : SLOPE_LR * y;
        y = a4.z * x.z + h4.z; acc.z += y > 0.f ? y : SLOPE_LR * y;
        y = a4.w * x.w + h4.w; acc.w += y > 0.f ? y : SLOPE_LR * y;
    }
    float r = 1.0f / (float)max(j1 - j0, 1);
    float4 o;
    o.x = to_tf32(acc.x * r); o.y = to_tf32(acc.y * r);
    o.z = to_tf32(acc.z * r); o.w = to_tf32(acc.w * r);
    reinterpret_cast<float4*>(out)[(size_t)node * 64 + lane] = o;
}

__global__ void round_kernel(const float* __restrict__ in, float* __restrict__ out, int n4) {
    int i = blockIdx.x * blockDim.x + threadIdx.x;
    if (i >= n4) return;
    float4 v = reinterpret_cast<const float4*>(in)[i];
    float4 o;
    o.x = to_tf32(v.x); o.y = to_tf32(v.y); o.z = to_tf32(v.z); o.w = to_tf32(v.w);
    reinterpret_cast<float4*>(out)[i] = o;
}

// ---------------- batched weight combine ----------------
struct WDesc {
    const float* A1; const float* B1;
    const float* A2; const float* B2;
    float* out;
    int astride, d, ostride, ocoff;
    float scale;
    int tile0;
};
struct WDescPack { WDesc w[10]; };

__global__ __launch_bounds__(256) void combine_w_batched(WDescPack p) {
    __shared__ float As[32][68];
    __shared__ float Bs[32][68];
    int bid = blockIdx.x;
    int di = 0;
#pragma unroll
    for (int i = 1; i < 10; i++)
        if (bid >= p.w[i].tile0) di = i;
    const WDesc w = p.w[di];
    int lt = bid - w.tile0;
    int ncols = w.d >> 6;
    int mtile = lt / ncols, ntile = lt % ncols;
    int m0 = mtile * 64, n0 = ntile * 64;

    int tid = threadIdx.x;
    int tx = tid & 15, ty = tid >> 4;

    float acc[4][4];
#pragma unroll
    for (int i = 0; i < 4; i++)
#pragma unroll
        for (int j = 0; j < 4; j++) acc[i][j] = 0.f;

    for (int term = 0; term < 2; term++) {
        const float* A = term ? w.A2 : w.A1;
        const float* B = term ? w.B2 : w.B1;
        if (!A) break;
        for (int kc = 0; kc < 256; kc += 32) {
            __syncthreads();
#pragma unroll
            for (int q = 0; q < 2; q++) {
                int s = tid + q * 256;
                int m = s >> 3, k4 = s & 7;
                float4 a = *reinterpret_cast<const float4*>(
                    A + (size_t)(m0 + m) * w.astride + kc + k4 * 4);
                As[k4 * 4 + 0][m] = a.x; As[k4 * 4 + 1][m] = a.y;
                As[k4 * 4 + 2][m] = a.z; As[k4 * 4 + 3][m] = a.w;
            }
#pragma unroll
            for (int q = 0; q < 2; q++) {
                int s = tid + q * 256;
                int k = s >> 4, n4 = s & 15;
                float4 b = *reinterpret_cast<const float4*>(
                    B + (size_t)(kc + k) * w.d + n0 + n4 * 4);
                *reinterpret_cast<float4*>(&Bs[k][n4 * 4]) = b;
            }
            __syncthreads();
#pragma unroll
            for (int k = 0; k < 32; k++) {
                float4 a = *reinterpret_cast<const float4*>(&As[k][ty * 4]);
                float4 b = *reinterpret_cast<const float4*>(&Bs[k][tx * 4]);
                float av[4] = {a.x, a.y, a.z, a.w};
                float bv[4] = {b.x, b.y, b.z, b.w};
#pragma unroll
                for (int i = 0; i < 4; i++)
#pragma unroll
                    for (int j = 0; j < 4; j++)
                        acc[i][j] = fmaf(av[i], bv[j], acc[i][j]);
            }
        }
    }

#pragma unroll
    for (int i = 0; i < 4; i++) {
        int o = m0 + ty * 4 + i;
#pragma unroll
        for (int j = 0; j < 4; j++)
            w.out[(size_t)o * w.ostride + w.ocoff + n0 + tx * 4 + j] =
                to_tf32(w.scale * acc[i][j]);
    }
}

struct BDesc {
    const float* W1; const float* bsrc1; const float* bdst1; const float* bupd1;
    const float* W2; const float* bsrc2; const float* bdst2; const float* bupd2;
    float* out; float scale;
};
struct BDescPack { BDesc b[4]; };

__global__ void combine_b_batched(BDescPack p) {
    const BDesc d = p.b[blockIdx.x];
    int o = threadIdx.x;
    float total = 0.f;
    {
        float acc = d.bupd1[o];
        const float* wrow = d.W1 + (size_t)o * 512;
#pragma unroll 4
        for (int i = 0; i < HD; i++)
            acc += wrow[i] * d.bdst1[i] + wrow[HD + i] * d.bsrc1[i];
        total += acc;
    }
    if (d.W2) {
        float acc = d.bupd2[o];
        const float* wrow = d.W2 + (size_t)o * 512;
#pragma unroll 4
        for (int i = 0; i < HD; i++)
            acc += wrow[i] * d.bdst2[i] + wrow[HD + i] * d.bsrc2[i];
        total += acc;
    }
    d.out[o] = d.scale * total;
}

// ---------------- TF32 tensor-core GEMM + fused BN-stats epilogue ----------------
// C[M,256] = [A0|A1|A2] @ W^T + bias; per-row-block column sum/sumsq -> part.
__global__ __launch_bounds__(256, 2) void gemm_tf32_kernel(
    const float* __restrict__ A0, int K0,
    const float* __restrict__ A1, int K1,
    const float* __restrict__ A2, int K2,
    const float* __restrict__ W, const float* __restrict__ bias,
    float* __restrict__ C, int M, float* __restrict__ part) {
    extern __shared__ float sm_[];
    const int Ktot = K0 + K1 + K2;
    int tid = threadIdx.x;
    int m0 = blockIdx.y * 128;
    int n0 = blockIdx.x * 128;
    int warp = tid >> 5, lane = tid & 31;
    int wm = (warp & 3) * 32;
    int wn = (warp >> 2) * 64;
    int lr = lane >> 2;
    int lc = lane & 3;
    uint32_t sbase = (uint32_t)__cvta_generic_to_shared(sm_);

    float acc[2][8][4];
#pragma unroll
    for (int mt = 0; mt < 2; mt++)
#pragma unroll
        for (int nt = 0; nt < 8; nt++)
#pragma unroll
            for (int q = 0; q < 4; q++) acc[mt][nt][q] = 0.f;

    auto issue = [&](int kb, int b) {
        const float* Ap; int sw, kl;
        if (kb < K0)           { Ap = A0; sw = K0; kl = kb; }
        else if (kb < K0 + K1) { Ap = A1; sw = K1; kl = kb - K0; }
        else                   { Ap = A2; sw = K2; kl = kb - K0 - K1; }
        uint32_t bb = sbase + b * (GEMM_BUF * 4);
#pragma unroll
        for (int q = 0; q < 4; q++) {
            int s = tid + q * 256;
            int m = s >> 3;
            int kq = s & 7;
            int gm = m0 + m;
            cp16(bb + (m * APAD + kq * 4) * 4,
                 Ap + (size_t)gm * sw + kl + kq * 4, gm < M ? 16 : 0);
            cp16(bb + (128 * APAD + m * APAD + kq * 4) * 4,
                 W + (size_t)(n0 + m) * Ktot + kb + kq * 4, 16);
        }
        asm volatile("cp.async.commit_group;");
    };

    int nslab = Ktot / 32;
    issue(0, 0);
    for (int is = 0; is < nslab; is++) {
        asm volatile("cp.async.wait_group 0;");
        __syncthreads();
        if (is + 1 < nslab) issue((is + 1) * 32, (is + 1) & 1);
        const float* As = sm_ + (is & 1) * GEMM_BUF;
        const float* Bs = As + 128 * APAD;

#pragma unroll
        for (int ks = 0; ks < 4; ks++) {
            int k0 = ks * 8;
            uint32_t af[2][4];
#pragma unroll
            for (int mt = 0; mt < 2; mt++) {
                int row = wm + mt * 16 + lr;
                af[mt][0] = __float_as_uint(As[row * APAD + k0 + lc]);
                af[mt][1] = __float_as_uint(As[(row + 8) * APAD + k0 + lc]);
                af[mt][2] = __float_as_uint(As[row * APAD + k0 + 4 + lc]);
                af[mt][3] = __float_as_uint(As[(row + 8) * APAD + k0 + 4 + lc]);
            }
#pragma unroll
            for (int nt = 0; nt < 8; nt++) {
                int col = wn + nt * 8 + lr;
                uint32_t b0 = __float_as_uint(Bs[col * APAD + k0 + lc]);
                uint32_t b1 = __float_as_uint(Bs[col * APAD + k0 + 4 + lc]);
#pragma unroll
                for (int mt = 0; mt < 2; mt++) {
                    asm volatile(
                        "mma.sync.aligned.m16n8k8.row.col.f32.tf32.tf32.f32 "
                        "{%0,%1,%2,%3}, {%4,%5,%6,%7}, {%8,%9}, {%0,%1,%2,%3};"
                        : "+f"(acc[mt][nt][0]), "+f"(acc[mt][nt][1]),
                          "+f"(acc[mt][nt][2]), "+f"(acc[mt][nt][3])
                        : "r"(af[mt][0]), "r"(af[mt][1]), "r"(af[mt][2]), "r"(af[mt][3]),
                          "r"(b0), "r"(b1));
                }
            }
        }
    }

    // ---- epilogue: store C and fused column sum/sumsq (smem buffers are dead now) ----
    __syncthreads();
    float* csum = sm_;
    float* csq = sm_ + 128;
    if (tid < 256) sm_[tid] = 0.f;
    __syncthreads();

#pragma unroll
    for (int nt = 0; nt < 8; nt++) {
        int gn = n0 + wn + nt * 8 + lc * 2;
        float b0 = bias[gn], b1 = bias[gn + 1];
        float s0 = 0.f, q0 = 0.f, s1 = 0.f, q1 = 0.f;
#pragma unroll
        for (int mt = 0; mt < 2; mt++) {
            int gm = m0 + wm + mt * 16 + lr;
            float y0 = acc[mt][nt][0] + b0;
            float y1 = acc[mt][nt][1] + b1;
            float y2 = acc[mt][nt][2] + b0;
            float y3 = acc[mt][nt][3] + b1;
            if (gm < M) {
                *reinterpret_cast<float2*>(C + (size_t)gm * 256 + gn) = make_float2(y0, y1);
                s0 += y0; q0 += y0 * y0; s1 += y1; q1 += y1 * y1;
            }
            if (gm + 8 < M) {
                *reinterpret_cast<float2*>(C + (size_t)(gm + 8) * 256 + gn) = make_float2(y2, y3);
                s0 += y2; q0 += y2 * y2; s1 += y3; q1 += y3 * y3;
            }
        }
#pragma unroll
        for (int m = 16; m >= 4; m >>= 1) {
            s0 += __shfl_xor_sync(0xffffffffu, s0, m);
            q0 += __shfl_xor_sync(0xffffffffu, q0, m);
            s1 += __shfl_xor_sync(0xffffffffu, s1, m);
            q1 += __shfl_xor_sync(0xffffffffu, q1, m);
        }
        if (lr == 0) {
            int cl = wn + nt * 8 + lc * 2;
            atomicAdd(&csum[cl], s0); atomicAdd(&csq[cl], q0);
            atomicAdd(&csum[cl + 1], s1); atomicAdd(&csq[cl + 1], q1);
        }
    }
    __syncthreads();
    if (tid < 128) {
        part[(size_t)blockIdx.y * 512 + n0 + tid] = csum[tid];
        part[(size_t)blockIdx.y * 512 + 256 + n0 + tid] = csq[tid];
    }
}

__global__ void bn_finalize_kernel(const float* __restrict__ part,
                                   const float* __restrict__ g, const float* __restrict__ bb,
                                   int M, float* __restrict__ sc, float* __restrict__ sh) {
    int t = threadIdx.x;
    float s = 0.f, s2 = 0.f;
    for (int blk = 0; blk < NBY; blk++) {
        s += part[(size_t)blk * 512 + t];
        s2 += part[(size_t)blk * 512 + 256 + t];
    }
    float mean = s / (float)M;
    float var = s2 / (float)M - mean * mean;
    float a = g[t] * rsqrtf(var + EPS_BN);
    sc[t] = a;
    sh[t] = bb[t] - mean * a;
}

__global__ void bn_apply_kernel(const float* __restrict__ X,
                                const float* __restrict__ sc, const float* __restrict__ sh,
                                float* __restrict__ Y, int M, int do_round) {
    int i = blockIdx.x * blockDim.x + threadIdx.x;
    if (i >= M * 64) return;
    int c4 = i & 63;
    float4 a = reinterpret_cast<const float4*>(sc)[c4];
    float4 c = reinterpret_cast<const float4*>(sh)[c4];
    float4 x = reinterpret_cast<const float4*>(X)[i];
    float4 y;
    y.x = a.x * x.x + c.x; y.x = y.x > 0.f ? y.x : SLOPE_LR * y.x;
    y.y = a.y * x.y + c.y; y.y = y.y > 0.f ? y.y : SLOPE_LR * y.y;
    y.z = a.z * x.z + c.z; y.z = y.z > 0.f ? y.z : SLOPE_LR * y.z;
    y.w = a.w * x.w + c.w; y.w = y.w > 0.f ? y.w : SLOPE_LR * y.w;
    if (do_round) {
        y.x = to_tf32(y.x); y.y = to_tf32(y.y); y.z = to_tf32(y.z); y.w = to_tf32(y.w);
    }
    reinterpret_cast<float4*>(Y)[i] = y;
}

// ---------------- host orchestration ----------------
static inline float* symf(const void* s) {
    void* p = nullptr;
    cudaGetSymbolAddress(&p, s);
    return (float*)p;
}
static inline int* symi(const void* s) {
    void* p = nullptr;
    cudaGetSymbolAddress(&p, s);
    return (int*)p;
}

extern "C" void kernel_launch(void* const* d_in, const int* in_sizes, int n_in,
                              void* d_out, int out_size) {
    (void)in_sizes; (void)n_in; (void)out_size;
    const float* x_A = (const float*)d_in[0];
    const float* x_B = (const float*)d_in[1];
    const int* e_ab = (const int*)d_in[2];
    const int* e_ba = (const int*)d_in[3];
    const int* e_aa = (const int*)d_in[4];
    const float* ab_Wsrc1 = (const float*)d_in[5];
    const float* ab_bsrc1 = (const float*)d_in[6];
    const float* ab_Wdst1 = (const float*)d_in[7];
    const float* ab_bdst1 = (const float*)d_in[8];
    const float* ab_Wupd1 = (const float*)d_in[9];
    const float* ab_bupd1 = (const float*)d_in[10];
    const float* ba_Wsrc1 = (const float*)d_in[11];
    const float* ba_bsrc1 = (const float*)d_in[12];
    const float* ba_Wdst1 = (const float*)d_in[13];
    const float* ba_bdst1 = (const float*)d_in[14];
    const float* ba_Wupd1 = (const float*)d_in[15];
    const float* ba_bupd1 = (const float*)d_in[16];
    const float* aa_Wsrc1 = (const float*)d_in[17];
    const float* aa_bsrc1 = (const float*)d_in[18];
    const float* aa_Wdst1 = (const float*)d_in[19];
    const float* aa_bdst1 = (const float*)d_in[20];
    const float* aa_Wupd1 = (const float*)d_in[21];
    const float* aa_bupd1 = (const float*)d_in[22];
    const float* Wsrc2 = (const float*)d_in[23];
    const float* bsrc2 = (const float*)d_in[24];
    const float* Wdst2 = (const float*)d_in[25];
    const float* bdst2 = (const float*)d_in[26];
    const float* Wupd2 = (const float*)d_in[27];
    const float* bupd2 = (const float*)d_in[28];
    const float* bn_g = (const float*)d_in[29];
    const float* bn_b = (const float*)d_in[30];
    float* out = (float*)d_out;

    float* aggr0 = symf(g_aggr0);
    float* aggr1 = symf(g_aggr1);
    float* aggr2 = symf(g_aggr2);
    float* hA = symf(g_hA);
    float* hB = symf(g_hB);
    float* preA = symf(g_preA);
    float* preB = symf(g_preB);
    float* xAt = symf(g_xAt);
    float* xBt = symf(g_xBt);
    int* icnt = symi(g_icnt);
    int* roff = symi(g_roff);
    int* csr = symi(g_csr);
    float* WA1 = symf(g_WA1);
    float* WB1 = symf(g_WB1);
    float* WA2 = symf(g_WA2);
    float* WB2 = symf(g_WB2);
    float* bA1 = symf(g_bA1);
    float* bB1 = symf(g_bB1);
    float* bA2 = symf(g_bA2);
    float* bB2 = symf(g_bB2);
    float* partA = symf(g_partA);
    float* partB = symf(g_partB);
    float* scA = symf(g_scA);
    float* shA = symf(g_shA);
    float* scB = symf(g_scB);
    float* shB = symf(g_shB);

    int* icnt_ab = icnt;          int* icnt_ba = icnt + NN;          int* icnt_aa = icnt + 2 * NN;
    int* roff_ab = roff;          int* roff_ba = roff + (NN + 1);    int* roff_aa = roff + 2 * (NN + 1);
    int* csr_ab = csr;            int* csr_ba = csr + NE;            int* csr_aa = csr + 2 * NE;

    const int EB = (NE + 255) / 256;
    const int G256 = (NN + 3) / 4;
    const int G128 = (NN + 7) / 8;
    dim3 ggrid(2, NBY);

    // one-time resources
    static cudaStream_t sW = nullptr, sB = nullptr, sC = nullptr;
    static cudaEvent_t evFork, evZero, evW, evAb, evBa, evAa, evStatsA, evG0, evG1, evDone;
    static bool inited = false;
    if (!inited) {
        inited = true;
        cudaStreamCreateWithFlags(&sW, cudaStreamNonBlocking);
        cudaStreamCreateWithFlags(&sB, cudaStreamNonBlocking);
        cudaStreamCreateWithFlags(&sC, cudaStreamNonBlocking);
        cudaEventCreateWithFlags(&evFork, cudaEventDisableTiming);
        cudaEventCreateWithFlags(&evZero, cudaEventDisableTiming);
        cudaEventCreateWithFlags(&evW, cudaEventDisableTiming);
        cudaEventCreateWithFlags(&evAb, cudaEventDisableTiming);
        cudaEventCreateWithFlags(&evBa, cudaEventDisableTiming);
        cudaEventCreateWithFlags(&evAa, cudaEventDisableTiming);
        cudaEventCreateWithFlags(&evStatsA, cudaEventDisableTiming);
        cudaEventCreateWithFlags(&evG0, cudaEventDisableTiming);
        cudaEventCreateWithFlags(&evG1, cudaEventDisableTiming);
        cudaEventCreateWithFlags(&evDone, cudaEventDisableTiming);
        cudaFuncSetAttribute(gemm_tf32_kernel,
                             cudaFuncAttributeMaxDynamicSharedMemorySize, GEMM_SMEM);
    }

    // ---- descriptor packs (pointers rebuilt every call) ----
    WDescPack wp;
    {
        int t = 0; int i = 0;
        auto add = [&](const float* A1, const float* B1, const float* A2, const float* B2,
                       float* o, int ostride, int ocoff, int d, float scale) {
            wp.w[i] = {A1, B1, A2, B2, o, 512, d, ostride, ocoff, scale, t};
            t += 4 * (d >> 6); i++;
        };
        add(ba_Wupd1, ba_Wdst1, aa_Wupd1, aa_Wdst1, WA1, 640, 0, 256, 0.5f);
        add(ba_Wupd1 + 256, ba_Wsrc1, nullptr, nullptr, WA1, 640, 256, 128, 0.5f);
        add(aa_Wupd1 + 256, aa_Wsrc1, nullptr, nullptr, WA1, 640, 384, 256, 0.5f);
        add(ab_Wupd1, ab_Wdst1, nullptr, nullptr, WB1, 384, 0, 128, 1.0f);
        add(ab_Wupd1 + 256, ab_Wsrc1, nullptr, nullptr, WB1, 384, 128, 256, 1.0f);
        add(Wupd2 + 131072, Wdst2 + 65536, Wupd2 + 262144, Wdst2 + 131072, WA2, 768, 0, 256, 0.5f);
        add(Wupd2 + 131072 + 256, Wsrc2 + 65536, nullptr, nullptr, WA2, 768, 256, 256, 0.5f);
        add(Wupd2 + 262144 + 256, Wsrc2 + 131072, nullptr, nullptr, WA2, 768, 512, 256, 0.5f);
        add(Wupd2, Wdst2, nullptr, nullptr, WB2, 512, 0, 256, 1.0f);
        add(Wupd2 + 256, Wsrc2, nullptr, nullptr, WB2, 512, 256, 256, 1.0f);
    }
    BDescPack bp;
    bp.b[0] = {ba_Wupd1, ba_bsrc1, ba_bdst1, ba_bupd1,
               aa_Wupd1, aa_bsrc1, aa_bdst1, aa_bupd1, bA1, 0.5f};
    bp.b[1] = {ab_Wupd1, ab_bsrc1, ab_bdst1, ab_bupd1,
               nullptr, nullptr, nullptr, nullptr, bB1, 1.0f};
    bp.b[2] = {Wupd2 + 131072, bsrc2 + 256, bdst2 + 256, bupd2 + 256,
               Wupd2 + 262144, bsrc2 + 512, bdst2 + 512, bupd2 + 512, bA2, 0.5f};
    bp.b[3] = {Wupd2, bsrc2, bdst2, bupd2,
               nullptr, nullptr, nullptr, nullptr, bB2, 1.0f};

    // ---- fork ----
    cudaEventRecord(evFork, 0);
    cudaStreamWaitEvent(sW, evFork, 0);

    zero_int_kernel<<<(3 * NN + 255) / 256, 256>>>(icnt, 3 * NN);
    cudaEventRecord(evZero, 0);
    cudaStreamWaitEvent(sB, evZero, 0);
    cudaStreamWaitEvent(sC, evZero, 0);

    // stream sW: input rounding + batched combines
    round_kernel<<<G256, 256, 0, sW>>>(x_A, xAt, NN * 64);
    round_kernel<<<G128, 256, 0, sW>>>(x_B, xBt, NN * 32);
    combine_w_batched<<<144, 256, 0, sW>>>(wp);
    combine_b_batched<<<4, 256, 0, sW>>>(bp);
    cudaEventRecord(evW, sW);

    // stream sB: ba chain
    count_int_kernel<<<EB, 256, 0, sB>>>(e_ba + NE, icnt_ba, NE);
    scan_kernel<<<1, 1024, 0, sB>>>(icnt_ba, roff_ba);
    fill_kernel<<<EB, 256, 0, sB>>>(e_ba, e_ba + NE, roff_ba, icnt_ba, csr_ba, NE);
    gather128_kernel<<<G128, 256, 0, sB>>>(x_B, roff_ba, csr_ba, aggr1);
    cudaEventRecord(evBa, sB);

    // stream sC: aa chain
    count_int_kernel<<<EB, 256, 0, sC>>>(e_aa + NE, icnt_aa, NE);
    scan_kernel<<<1, 1024, 0, sC>>>(icnt_aa, roff_aa);
    fill_kernel<<<EB, 256, 0, sC>>>(e_aa, e_aa + NE, roff_aa, icnt_aa, csr_aa, NE);
    gather256_kernel<<<G256, 256, 0, sC>>>(x_A, roff_aa, csr_aa, aggr2);
    cudaEventRecord(evAa, sC);

    // default stream: ab chain
    count_int_kernel<<<EB, 256>>>(e_ab + NE, icnt_ab, NE);
    scan_kernel<<<1, 1024>>>(icnt_ab, roff_ab);
    fill_kernel<<<EB, 256>>>(e_ab, e_ab + NE, roff_ab, icnt_ab, csr_ab, NE);
    gather256_kernel<<<G256, 256>>>(x_A, roff_ab, csr_ab, aggr0);
    cudaEventRecord(evAb, 0);

    // ---- layer 1 A-side (default stream) ----
    cudaStreamWaitEvent(0, evW, 0);
    cudaStreamWaitEvent(0, evBa, 0);
    cudaStreamWaitEvent(0, evAa, 0);
    gemm_tf32_kernel<<<ggrid, 256, GEMM_SMEM>>>(xAt, 256, aggr1, 128, aggr2, 256,
                                                WA1, bA1, preA, NN, partA);
    bn_finalize_kernel<<<1, 256>>>(partA, bn_g + 0, bn_b + 0, NN, scA, shA);
    cudaEventRecord(evStatsA, 0);
    // L2 aa gather reads preA + BN inline (no bn_apply dependency)
    gather256_bn_kernel<<<G256, 256>>>(preA, roff_aa, csr_aa, scA, shA, aggr2);
    bn_apply_kernel<<<G256, 256>>>(preA, scA, shA, hA, NN, 1);   // hA for L2 GEMM A0

    // ---- layer 1 B-side (sB) ----
    cudaStreamWaitEvent(sB, evAb, 0);
    cudaStreamWaitEvent(sB, evW, 0);
    gemm_tf32_kernel<<<ggrid, 256, GEMM_SMEM, sB>>>(xBt, 128, aggr0, 256, nullptr, 0,
                                                    WB1, bB1, preB, NN, partB);
    bn_finalize_kernel<<<1, 256, 0, sB>>>(partB, bn_g + 256, bn_b + 256, NN, scB, shB);
    gather256_bn_kernel<<<G256, 256, 0, sB>>>(preB, roff_ba, csr_ba, scB, shB, aggr1);
    cudaEventRecord(evG1, sB);
    bn_apply_kernel<<<G256, 256, 0, sB>>>(preB, scB, shB, hB, NN, 1);  // hB for L2 GEMM B0

    // stream sC: L2 ab gather (preA + BN inline)
    cudaStreamWaitEvent(sC, evStatsA, 0);
    gather256_bn_kernel<<<G256, 256, 0, sC>>>(preA, roff_ab, csr_ab, scA, shA, aggr0);
    cudaEventRecord(evG0, sC);

    // ---- layer 2 A-side (default stream) ----
    cudaStreamWaitEvent(0, evG1, 0);
    cudaStreamWaitEvent(0, evG0, 0);   // WAR: gemmA2 overwrites preA, which sC's gather reads
    gemm_tf32_kernel<<<ggrid, 256, GEMM_SMEM>>>(hA, 256, aggr1, 256, aggr2, 256,
                                                WA2, bA2, preA, NN, partA);
    bn_finalize_kernel<<<1, 256>>>(partA, bn_g + 512, bn_b + 512, NN, scA, shA);
    bn_apply_kernel<<<G256, 256>>>(preA, scA, shA, out, NN, 0);

    // ---- layer 2 B-side (sB) ----
    cudaStreamWaitEvent(sB, evG0, 0);
    gemm_tf32_kernel<<<ggrid, 256, GEMM_SMEM, sB>>>(hB, 256, aggr0, 256, nullptr, 0,
                                                    WB2, bB2, preB, NN, partB);
    bn_finalize_kernel<<<1, 256, 0, sB>>>(partB, bn_g + 768, bn_b + 768, NN, scB, shB);
    bn_apply_kernel<<<G256, 256, 0, sB>>>(preB, scB, shB, out + (size_t)NN * HD, NN, 0);
    cudaEventRecord(evDone, sB);

    cudaStreamWaitEvent(0, evDone, 0);
}